// round 5
// baseline (speedup 1.0000x reference)
#include <cuda_runtime.h>
#include <stdint.h>

#define NN      8192
#define EE      262144
#define IN_NODE 11
#define IN_EDGE 4
#define IN_NF   15
#define H_NF    4
#define OUT_NF  4
#define EMB_NF  2
#define NREP    4

// Scratch -------------------------------------------------------------------
// Invariant: g_acc is all-zero at entry of every kernel_launch call.
// (Zero at module load; k_emb re-zeroes after consuming.)
__device__ float2 g_acc[NREP][NN];
__device__ float  g_emb2[NN * EMB_NF];

// M[a][c] = sum_b W2[a][b] * We[b][c]
__device__ __forceinline__ void fuse_W2We(const float* __restrict__ W2,
                                          const float* __restrict__ We,
                                          float M[H_NF][EMB_NF]) {
#pragma unroll
    for (int a = 0; a < H_NF; a++)
#pragma unroll
        for (int c = 0; c < EMB_NF; c++) {
            float acc = 0.0f;
#pragma unroll
            for (int b = 0; b < OUT_NF; b++)
                acc += __ldg(&W2[a * OUT_NF + b]) * __ldg(&We[b * EMB_NF + c]);
            M[a][c] = acc;
        }
}

// ---------------------------------------------------------------------------
// Kernel 1: scatter edge contributions. One red.v2 per edge into a 4-way
// replicated accumulator (contention /8 vs round 4).
// ---------------------------------------------------------------------------
__global__ void __launch_bounds__(256) k_scatter(
        const int* __restrict__ edge_index, const float* __restrict__ edge_attr,
        const float* __restrict__ W1, const float* __restrict__ W2,
        const float* __restrict__ We) {
    float M[H_NF][EMB_NF];
    fuse_W2We(W2, We, M);
    float wfe[IN_EDGE][EMB_NF];
#pragma unroll
    for (int r = 0; r < IN_EDGE; r++)
#pragma unroll
        for (int c = 0; c < EMB_NF; c++) {
            float acc = 0.0f;
#pragma unroll
            for (int a = 0; a < H_NF; a++)
                acc += __ldg(&W1[(IN_NODE + r) * H_NF + a]) * M[a][c];
            wfe[r][c] = acc;
        }

    int e = blockIdx.x * blockDim.x + threadIdx.x;
    if (e >= EE) return;
    int rr = edge_index[e];                       // edge_index[0][e] (int32)
    float4 a = reinterpret_cast<const float4*>(edge_attr)[e];
    float cx = a.x * wfe[0][0] + a.y * wfe[1][0] + a.z * wfe[2][0] + a.w * wfe[3][0];
    float cy = a.x * wfe[0][1] + a.y * wfe[1][1] + a.z * wfe[2][1] + a.w * wfe[3][1];

    float2* dst = &g_acc[blockIdx.x & (NREP - 1)][rr];
    asm volatile("red.global.add.v2.f32 [%0], {%1, %2};"
                 :: "l"(dst), "f"(cx), "f"(cy) : "memory");
}

// ---------------------------------------------------------------------------
// Kernel 2: per-node embedding; sums 4 replicas, re-zeroes them.
// ---------------------------------------------------------------------------
__global__ void __launch_bounds__(256) k_emb(
        const float* __restrict__ node_feats,
        const float* __restrict__ W1, const float* __restrict__ b1,
        const float* __restrict__ W2, const float* __restrict__ b2,
        const float* __restrict__ We, const float* __restrict__ be,
        float* __restrict__ out_emb) {
    float M[H_NF][EMB_NF];
    fuse_W2We(W2, We, M);
    float wfn[IN_NODE][EMB_NF];
#pragma unroll
    for (int k = 0; k < IN_NODE; k++)
#pragma unroll
        for (int c = 0; c < EMB_NF; c++) {
            float acc = 0.0f;
#pragma unroll
            for (int a = 0; a < H_NF; a++)
                acc += __ldg(&W1[k * H_NF + a]) * M[a][c];
            wfn[k][c] = acc;
        }
    float bf[EMB_NF];
#pragma unroll
    for (int c = 0; c < EMB_NF; c++) {
        float acc = __ldg(&be[c]);
#pragma unroll
        for (int b = 0; b < OUT_NF; b++) {
            float hb = __ldg(&b2[b]);
#pragma unroll
            for (int a = 0; a < H_NF; a++)
                hb += __ldg(&b1[a]) * __ldg(&W2[a * OUT_NF + b]);
            acc += hb * __ldg(&We[b * EMB_NF + c]);
        }
        bf[c] = acc;
    }

    int i = blockIdx.x * blockDim.x + threadIdx.x;
    if (i >= NN) return;
    float ex = bf[0], ey = bf[1];
#pragma unroll
    for (int r = 0; r < NREP; r++) {
        float2 v = g_acc[r][i];
        ex += v.x;  ey += v.y;
        g_acc[r][i] = make_float2(0.0f, 0.0f);   // restore invariant
    }
#pragma unroll
    for (int k = 0; k < IN_NODE; k++) {
        float nf = node_feats[i * IN_NODE + k];
        ex += nf * wfn[k][0];
        ey += nf * wfn[k][1];
    }
    g_emb2[i * 2 + 0] = ex;
    g_emb2[i * 2 + 1] = ey;
    out_emb[i * 2 + 0] = ex;
    out_emb[i * 2 + 1] = ey;
}

// ---------------------------------------------------------------------------
// Kernel 3: all-pairs adjacency. 4 rows/CTA, 8 cols/thread/iter, streaming
// float4 stores, no diagonal predicate in the hot loop.
// sigmoid(10d-1) = 1 / (1 + 2^(log2e - 10*log2e*d))
// ---------------------------------------------------------------------------
#define NEG10_LOG2E  (-14.4269504088896341f)
#define LOG2E         (1.44269504088896341f)

__global__ void __launch_bounds__(256) k_pair(float* __restrict__ adj) {
    const int i0 = blockIdx.x * 4;
    float2 ei[4];
#pragma unroll
    for (int r = 0; r < 4; r++)
        ei[r] = reinterpret_cast<const float2*>(g_emb2)[i0 + r];

    const float4* embq = reinterpret_cast<const float4*>(g_emb2);

    for (int g = threadIdx.x; g < NN / 8; g += blockDim.x) {
        const int j0 = g * 8;
        float2 ej[8];
#pragma unroll
        for (int q = 0; q < 4; q++) {
            float4 v = embq[j0 / 2 + q];
            ej[q * 2 + 0] = make_float2(v.x, v.y);
            ej[q * 2 + 1] = make_float2(v.z, v.w);
        }

#pragma unroll
        for (int r = 0; r < 4; r++) {
            float o[8];
#pragma unroll
            for (int c = 0; c < 8; c++) {
                float dx = ei[r].x - ej[c].x;
                float dy = ei[r].y - ej[c].y;
                float d  = fmaf(dy, dy, dx * dx);
                float e  = exp2f(fmaf(d, NEG10_LOG2E, LOG2E));  // MUFU.EX2
                float s;
                asm("rcp.approx.f32 %0, %1;" : "=f"(s) : "f"(1.0f + e));
                o[c] = s;
            }
            float* base = adj + (size_t)(i0 + r) * NN + j0;
            __stcs(reinterpret_cast<float4*>(base),     make_float4(o[0], o[1], o[2], o[3]));
            __stcs(reinterpret_cast<float4*>(base) + 1, make_float4(o[4], o[5], o[6], o[7]));
        }
    }

    __syncthreads();
    if (threadIdx.x < 4) {
        int i = i0 + threadIdx.x;
        adj[(size_t)i * NN + i] = 0.0f;
    }
}

// ---------------------------------------------------------------------------
extern "C" void kernel_launch(void* const* d_in, const int* in_sizes, int n_in,
                              void* d_out, int out_size) {
    const float* node_feats = (const float*)d_in[0];
    const int*   edge_index = (const int*)d_in[1];
    const float* edge_attr  = (const float*)d_in[2];
    const float* W1 = (const float*)d_in[3];
    const float* b1 = (const float*)d_in[4];
    const float* W2 = (const float*)d_in[5];
    const float* b2 = (const float*)d_in[6];
    const float* We = (const float*)d_in[7];
    const float* be = (const float*)d_in[8];

    float* adj     = (float*)d_out;                       // [N, N]
    float* out_emb = (float*)d_out + (size_t)NN * NN;     // [N, 2]

    k_scatter<<<EE / 256, 256>>>(edge_index, edge_attr, W1, W2, We);
    k_emb<<<NN / 256, 256>>>(node_feats, W1, b1, W2, b2, We, be, out_emb);
    k_pair<<<NN / 4, 256>>>(adj);
}

// round 6
// speedup vs baseline: 1.5671x; 1.5671x over previous
#include <cuda_runtime.h>
#include <stdint.h>

#define NN      8192
#define EE      262144
#define IN_NODE 11
#define IN_EDGE 4
#define IN_NF   15
#define H_NF    4
#define OUT_NF  4
#define EMB_NF  2
#define NREP    8

// Scratch -------------------------------------------------------------------
// Invariant: g_acc is all-zero at entry of every kernel_launch call.
// (Zero at module load; k_emb re-zeroes after consuming.)
__device__ float2 g_acc[NREP][NN];
__device__ float  g_emb2[NN * EMB_NF];

// M[a][c] = sum_b W2[a][b] * We[b][c]
__device__ __forceinline__ void fuse_W2We(const float* __restrict__ W2,
                                          const float* __restrict__ We,
                                          float M[H_NF][EMB_NF]) {
#pragma unroll
    for (int a = 0; a < H_NF; a++)
#pragma unroll
        for (int c = 0; c < EMB_NF; c++) {
            float acc = 0.0f;
#pragma unroll
            for (int b = 0; b < OUT_NF; b++)
                acc += __ldg(&W2[a * OUT_NF + b]) * __ldg(&We[b * EMB_NF + c]);
            M[a][c] = acc;
        }
}

// ---------------------------------------------------------------------------
// Kernel 1: scatter edge contributions. One red.v2 per edge into an 8-way
// replicated accumulator (4-way per-address contention).
// ---------------------------------------------------------------------------
__global__ void __launch_bounds__(256) k_scatter(
        const int* __restrict__ edge_index, const float* __restrict__ edge_attr,
        const float* __restrict__ W1, const float* __restrict__ W2,
        const float* __restrict__ We) {
    float M[H_NF][EMB_NF];
    fuse_W2We(W2, We, M);
    float wfe[IN_EDGE][EMB_NF];
#pragma unroll
    for (int r = 0; r < IN_EDGE; r++)
#pragma unroll
        for (int c = 0; c < EMB_NF; c++) {
            float acc = 0.0f;
#pragma unroll
            for (int a = 0; a < H_NF; a++)
                acc += __ldg(&W1[(IN_NODE + r) * H_NF + a]) * M[a][c];
            wfe[r][c] = acc;
        }

    int e = blockIdx.x * blockDim.x + threadIdx.x;
    if (e >= EE) return;
    int rr = edge_index[e];                       // edge_index[0][e] (int32)
    float4 a = reinterpret_cast<const float4*>(edge_attr)[e];
    float cx = a.x * wfe[0][0] + a.y * wfe[1][0] + a.z * wfe[2][0] + a.w * wfe[3][0];
    float cy = a.x * wfe[0][1] + a.y * wfe[1][1] + a.z * wfe[2][1] + a.w * wfe[3][1];

    float2* dst = &g_acc[blockIdx.x & (NREP - 1)][rr];
    asm volatile("red.global.add.v2.f32 [%0], {%1, %2};"
                 :: "l"(dst), "f"(cx), "f"(cy) : "memory");
}

// ---------------------------------------------------------------------------
// Kernel 2: per-node embedding; sums replicas, re-zeroes them.
// ---------------------------------------------------------------------------
__global__ void __launch_bounds__(256) k_emb(
        const float* __restrict__ node_feats,
        const float* __restrict__ W1, const float* __restrict__ b1,
        const float* __restrict__ W2, const float* __restrict__ b2,
        const float* __restrict__ We, const float* __restrict__ be,
        float* __restrict__ out_emb) {
    float M[H_NF][EMB_NF];
    fuse_W2We(W2, We, M);
    float wfn[IN_NODE][EMB_NF];
#pragma unroll
    for (int k = 0; k < IN_NODE; k++)
#pragma unroll
        for (int c = 0; c < EMB_NF; c++) {
            float acc = 0.0f;
#pragma unroll
            for (int a = 0; a < H_NF; a++)
                acc += __ldg(&W1[k * H_NF + a]) * M[a][c];
            wfn[k][c] = acc;
        }
    float bf[EMB_NF];
#pragma unroll
    for (int c = 0; c < EMB_NF; c++) {
        float acc = __ldg(&be[c]);
#pragma unroll
        for (int b = 0; b < OUT_NF; b++) {
            float hb = __ldg(&b2[b]);
#pragma unroll
            for (int a = 0; a < H_NF; a++)
                hb += __ldg(&b1[a]) * __ldg(&W2[a * OUT_NF + b]);
            acc += hb * __ldg(&We[b * EMB_NF + c]);
        }
        bf[c] = acc;
    }

    int i = blockIdx.x * blockDim.x + threadIdx.x;
    if (i >= NN) return;
    float ex = bf[0], ey = bf[1];
#pragma unroll
    for (int r = 0; r < NREP; r++) {
        float2 v = g_acc[r][i];
        ex += v.x;  ey += v.y;
        g_acc[r][i] = make_float2(0.0f, 0.0f);   // restore invariant
    }
#pragma unroll
    for (int k = 0; k < IN_NODE; k++) {
        float nf = node_feats[i * IN_NODE + k];
        ex += nf * wfn[k][0];
        ey += nf * wfn[k][1];
    }
    g_emb2[i * 2 + 0] = ex;
    g_emb2[i * 2 + 1] = ey;
    out_emb[i * 2 + 0] = ex;
    out_emb[i * 2 + 1] = ey;
}

// ---------------------------------------------------------------------------
// Kernel 3: all-pairs adjacency. 4 rows/CTA, 4 cols/thread/iter — ONE fully
// coalesced float4 streaming store per row per iter (full 32B sectors per
// warp; the R5 split-store pattern caused DRAM RMW).
// sigmoid(10d-1) = 0.5*tanh(5d-0.5) + 0.5  (single MUFU.TANH)
// ---------------------------------------------------------------------------
__device__ __forceinline__ float sigmoid_tanh(float dsq) {
    float t;
    float x = fmaf(dsq, 5.0f, -0.5f);
    asm("tanh.approx.f32 %0, %1;" : "=f"(t) : "f"(x));
    return fmaf(t, 0.5f, 0.5f);
}

__global__ void __launch_bounds__(256) k_pair(float* __restrict__ adj) {
    const int i0 = blockIdx.x * 4;
    float2 ei[4];
#pragma unroll
    for (int r = 0; r < 4; r++)
        ei[r] = reinterpret_cast<const float2*>(g_emb2)[i0 + r];

    const float4* embq = reinterpret_cast<const float4*>(g_emb2);

    for (int g = threadIdx.x; g < NN / 4; g += blockDim.x) {
        const int j0 = g * 4;
        float2 ej[4];
#pragma unroll
        for (int q = 0; q < 2; q++) {
            float4 v = embq[g * 2 + q];
            ej[q * 2 + 0] = make_float2(v.x, v.y);
            ej[q * 2 + 1] = make_float2(v.z, v.w);
        }

#pragma unroll
        for (int r = 0; r < 4; r++) {
            float o[4];
#pragma unroll
            for (int c = 0; c < 4; c++) {
                float dx = ei[r].x - ej[c].x;
                float dy = ei[r].y - ej[c].y;
                float d  = fmaf(dy, dy, dx * dx);
                o[c] = sigmoid_tanh(d);
            }
            __stcs(reinterpret_cast<float4*>(adj + (size_t)(i0 + r) * NN + j0),
                   make_float4(o[0], o[1], o[2], o[3]));
        }
    }

    __syncthreads();
    if (threadIdx.x < 4) {
        int i = i0 + threadIdx.x;
        adj[(size_t)i * NN + i] = 0.0f;
    }
}

// ---------------------------------------------------------------------------
extern "C" void kernel_launch(void* const* d_in, const int* in_sizes, int n_in,
                              void* d_out, int out_size) {
    const float* node_feats = (const float*)d_in[0];
    const int*   edge_index = (const int*)d_in[1];
    const float* edge_attr  = (const float*)d_in[2];
    const float* W1 = (const float*)d_in[3];
    const float* b1 = (const float*)d_in[4];
    const float* W2 = (const float*)d_in[5];
    const float* b2 = (const float*)d_in[6];
    const float* We = (const float*)d_in[7];
    const float* be = (const float*)d_in[8];

    float* adj     = (float*)d_out;                       // [N, N]
    float* out_emb = (float*)d_out + (size_t)NN * NN;     // [N, 2]

    k_scatter<<<EE / 256, 256>>>(edge_index, edge_attr, W1, W2, We);
    k_emb<<<NN / 256, 256>>>(node_feats, W1, b1, W2, b2, We, be, out_emb);
    k_pair<<<NN / 4, 256>>>(adj);
}

// round 7
// speedup vs baseline: 1.5803x; 1.0084x over previous
#include <cuda_runtime.h>
#include <stdint.h>

#define NN      8192
#define EE      262144
#define IN_NODE 11
#define IN_EDGE 4
#define IN_NF   15
#define H_NF    4
#define OUT_NF  4
#define EMB_NF  2
#define NREP    8

#define ROWS    8          // rows per CTA in k_pair
#define EPT     4          // edges per thread in k_scatter

// Scratch -------------------------------------------------------------------
// Invariant: g_acc is all-zero at entry of every kernel_launch call.
// (Zero at module load; k_emb re-zeroes after consuming.)
__device__ float2 g_acc[NREP][NN];
__device__ float  g_emb2[NN * EMB_NF];

// M[a][c] = sum_b W2[a][b] * We[b][c]
__device__ __forceinline__ void fuse_W2We(const float* __restrict__ W2,
                                          const float* __restrict__ We,
                                          float M[H_NF][EMB_NF]) {
#pragma unroll
    for (int a = 0; a < H_NF; a++)
#pragma unroll
        for (int c = 0; c < EMB_NF; c++) {
            float acc = 0.0f;
#pragma unroll
            for (int b = 0; b < OUT_NF; b++)
                acc += __ldg(&W2[a * OUT_NF + b]) * __ldg(&We[b * EMB_NF + c]);
            M[a][c] = acc;
        }
}

// ---------------------------------------------------------------------------
// Kernel 1: scatter edge contributions. 4 edges per thread (4 independent
// LDG->RED chains in flight), one red.v2 per edge, 8-way replicated target.
// ---------------------------------------------------------------------------
__global__ void __launch_bounds__(256) k_scatter(
        const int* __restrict__ edge_index, const float* __restrict__ edge_attr,
        const float* __restrict__ W1, const float* __restrict__ W2,
        const float* __restrict__ We) {
    float M[H_NF][EMB_NF];
    fuse_W2We(W2, We, M);
    float wfe[IN_EDGE][EMB_NF];
#pragma unroll
    for (int r = 0; r < IN_EDGE; r++)
#pragma unroll
        for (int c = 0; c < EMB_NF; c++) {
            float acc = 0.0f;
#pragma unroll
            for (int a = 0; a < H_NF; a++)
                acc += __ldg(&W1[(IN_NODE + r) * H_NF + a]) * M[a][c];
            wfe[r][c] = acc;
        }

    const int tid    = blockIdx.x * blockDim.x + threadIdx.x;
    const int stride = (EE / EPT);          // total threads
    const int rep    = blockIdx.x & (NREP - 1);

#pragma unroll
    for (int u = 0; u < EPT; u++) {
        int e = tid + u * stride;
        int rr = edge_index[e];             // edge_index[0][e] (int32)
        float4 a = reinterpret_cast<const float4*>(edge_attr)[e];
        float cx = a.x * wfe[0][0] + a.y * wfe[1][0] + a.z * wfe[2][0] + a.w * wfe[3][0];
        float cy = a.x * wfe[0][1] + a.y * wfe[1][1] + a.z * wfe[2][1] + a.w * wfe[3][1];
        float2* dst = &g_acc[rep][rr];
        asm volatile("red.global.add.v2.f32 [%0], {%1, %2};"
                     :: "l"(dst), "f"(cx), "f"(cy) : "memory");
    }
}

// ---------------------------------------------------------------------------
// Kernel 2: per-node embedding; sums replicas, re-zeroes them.
// ---------------------------------------------------------------------------
__global__ void __launch_bounds__(256) k_emb(
        const float* __restrict__ node_feats,
        const float* __restrict__ W1, const float* __restrict__ b1,
        const float* __restrict__ W2, const float* __restrict__ b2,
        const float* __restrict__ We, const float* __restrict__ be,
        float* __restrict__ out_emb) {
    float M[H_NF][EMB_NF];
    fuse_W2We(W2, We, M);
    float wfn[IN_NODE][EMB_NF];
#pragma unroll
    for (int k = 0; k < IN_NODE; k++)
#pragma unroll
        for (int c = 0; c < EMB_NF; c++) {
            float acc = 0.0f;
#pragma unroll
            for (int a = 0; a < H_NF; a++)
                acc += __ldg(&W1[k * H_NF + a]) * M[a][c];
            wfn[k][c] = acc;
        }
    float bf[EMB_NF];
#pragma unroll
    for (int c = 0; c < EMB_NF; c++) {
        float acc = __ldg(&be[c]);
#pragma unroll
        for (int b = 0; b < OUT_NF; b++) {
            float hb = __ldg(&b2[b]);
#pragma unroll
            for (int a = 0; a < H_NF; a++)
                hb += __ldg(&b1[a]) * __ldg(&W2[a * OUT_NF + b]);
            acc += hb * __ldg(&We[b * EMB_NF + c]);
        }
        bf[c] = acc;
    }

    int i = blockIdx.x * blockDim.x + threadIdx.x;
    if (i >= NN) return;
    float ex = bf[0], ey = bf[1];
#pragma unroll
    for (int r = 0; r < NREP; r++) {
        float2 v = g_acc[r][i];
        ex += v.x;  ey += v.y;
        g_acc[r][i] = make_float2(0.0f, 0.0f);   // restore invariant
    }
#pragma unroll
    for (int k = 0; k < IN_NODE; k++) {
        float nf = node_feats[i * IN_NODE + k];
        ex += nf * wfn[k][0];
        ey += nf * wfn[k][1];
    }
    g_emb2[i * 2 + 0] = ex;
    g_emb2[i * 2 + 1] = ey;
    out_emb[i * 2 + 0] = ex;
    out_emb[i * 2 + 1] = ey;
}

// ---------------------------------------------------------------------------
// Kernel 3: all-pairs adjacency, dot-product form.
//   5d - 0.5 = K_i + a_j - 10*ei.ej,  K_i = 5|ei|^2 - 0.5,  a_j = 5|ej|^2
//   sigmoid(10d-1) = 0.5*tanh(5d-0.5) + 0.5   (single MUFU.TANH)
// 8 rows/CTA, 4 cols/thread/iter, one coalesced STG.128 per row per iter.
// ---------------------------------------------------------------------------
__global__ void __launch_bounds__(256) k_pair(float* __restrict__ adj) {
    const int i0 = blockIdx.x * ROWS;
    float Kc[ROWS], bx[ROWS], by[ROWS];
#pragma unroll
    for (int r = 0; r < ROWS; r++) {
        float2 e = reinterpret_cast<const float2*>(g_emb2)[i0 + r];
        Kc[r] = fmaf(5.0f, fmaf(e.y, e.y, e.x * e.x), -0.5f);
        bx[r] = -10.0f * e.x;
        by[r] = -10.0f * e.y;
    }

    const float4* embq = reinterpret_cast<const float4*>(g_emb2);

    for (int g = threadIdx.x; g < NN / 4; g += blockDim.x) {
        const int j0 = g * 4;
        float2 ej[4];
        float  aj[4];
#pragma unroll
        for (int q = 0; q < 2; q++) {
            float4 v = embq[g * 2 + q];
            ej[q * 2 + 0] = make_float2(v.x, v.y);
            ej[q * 2 + 1] = make_float2(v.z, v.w);
        }
#pragma unroll
        for (int c = 0; c < 4; c++)
            aj[c] = 5.0f * fmaf(ej[c].y, ej[c].y, ej[c].x * ej[c].x);

#pragma unroll
        for (int r = 0; r < ROWS; r++) {
            float o[4];
#pragma unroll
            for (int c = 0; c < 4; c++) {
                float t = Kc[r] + aj[c];
                t = fmaf(bx[r], ej[c].x, t);
                t = fmaf(by[r], ej[c].y, t);
                float th;
                asm("tanh.approx.f32 %0, %1;" : "=f"(th) : "f"(t));
                o[c] = fmaf(th, 0.5f, 0.5f);
            }
            __stcs(reinterpret_cast<float4*>(adj + (size_t)(i0 + r) * NN + j0),
                   make_float4(o[0], o[1], o[2], o[3]));
        }
    }

    __syncthreads();
    if (threadIdx.x < ROWS) {
        int i = i0 + threadIdx.x;
        adj[(size_t)i * NN + i] = 0.0f;
    }
}

// ---------------------------------------------------------------------------
extern "C" void kernel_launch(void* const* d_in, const int* in_sizes, int n_in,
                              void* d_out, int out_size) {
    const float* node_feats = (const float*)d_in[0];
    const int*   edge_index = (const int*)d_in[1];
    const float* edge_attr  = (const float*)d_in[2];
    const float* W1 = (const float*)d_in[3];
    const float* b1 = (const float*)d_in[4];
    const float* W2 = (const float*)d_in[5];
    const float* b2 = (const float*)d_in[6];
    const float* We = (const float*)d_in[7];
    const float* be = (const float*)d_in[8];

    float* adj     = (float*)d_out;                       // [N, N]
    float* out_emb = (float*)d_out + (size_t)NN * NN;     // [N, 2]

    k_scatter<<<EE / EPT / 256, 256>>>(edge_index, edge_attr, W1, W2, We);
    k_emb<<<NN / 256, 256>>>(node_feats, W1, b1, W2, b2, We, be, out_emb);
    k_pair<<<NN / ROWS, 256>>>(adj);
}